// round 3
// baseline (speedup 1.0000x reference)
#include <cuda_runtime.h>
#include <math.h>

// Problem constants (fixed by setup_inputs)
#define B_  8
#define T_  4096
#define D_  1024
#define A_  32
#define S_  16
#define H_  256             // max(ttl*4, S*4)
#define W_  (H_ - S_ + 1)   // 241
#define NT  256
#define NPAIR (B_ * A_)     // 256
#define NCHUNK 4
#define DC (D_ / NCHUNK)    // 256 floats per chunk

// Cross-kernel scratch: every slot is written on every launch (deterministic,
// no zeroing, no atomics). __device__ globals are the sanctioned scratch path.
__device__ float g_ss [NCHUNK][NPAIR][H_];   // per-row squared-diff partials
__device__ float g_dot[NCHUNK][NPAIR];
__device__ float g_nf2[NCHUNK][NPAIR];
__device__ float g_na2[NCHUNK][NPAIR];

__device__ __forceinline__ unsigned long long compat_mask_of(int r) {
    switch (r) {
        case 11: return (1ull<<11)|(1ull<<13)|(1ull<<16);
        case 21: return (1ull<<14)|(1ull<<15)|(1ull<<21)|(1ull<<22)|(1ull<<23);
        case 31: return (1ull<<15)|(1ull<<31)|(1ull<<32)|(1ull<<33);
        case 41: return (1ull<<41)|(1ull<<42)|(1ull<<43)|(1ull<<44);
        case 51: return (1ull<<15)|(1ull<<51)|(1ull<<52)|(1ull<<53);
        default: return 0ull;
    }
}

__constant__ signed char c_alias[64] = {
    -1,-1,-1,-1,-1,-1,-1,-1,-1,-1,
    -1,11,-1,11,-1,-1,11,-1,-1,-1,
    -1,21,21,21,-1,-1,-1,-1,-1,-1,
    -1,31,31,31,-1,-1,-1,-1,-1,-1,
    -1,41,41,41,41,-1,-1,-1,-1,-1,
    -1,51,51,51,-1,-1,-1,-1,-1,-1,
    -1,-1,-1,-1
};

__device__ __forceinline__ float blockReduceSum(float v, float* s_red, int tid) {
    s_red[tid] = v; __syncthreads();
    #pragma unroll
    for (int o = NT/2; o > 0; o >>= 1) {
        if (tid < o) s_red[tid] += s_red[tid + o];
        __syncthreads();
    }
    float r = s_red[0]; __syncthreads();
    return r;
}

__device__ __forceinline__ float blockReduceMax(float v, float* s_red, int tid) {
    s_red[tid] = v; __syncthreads();
    #pragma unroll
    for (int o = NT/2; o > 0; o >>= 1) {
        if (tid < o) s_red[tid] = fmaxf(s_red[tid], s_red[tid + o]);
        __syncthreads();
    }
    float r = s_red[0]; __syncthreads();
    return r;
}

// ---------------------------------------------------------------------------
// Kernel 1: heavy streaming pass. grid = NPAIR*NCHUNK, one (pair, d-chunk) per CTA.
// Warp w handles rows {w, w+8, ...}; each lane owns 8 floats (2 float4) of chunk.
// ---------------------------------------------------------------------------
__global__ __launch_bounds__(NT, 4)
void cm_heavy(const float* __restrict__ hidden,
              const float* __restrict__ anchor_repr,
              const int*   __restrict__ anchor_end)
{
    __shared__ float s_m[DC];    // chunk-local sum over all H rows
    __shared__ float s_red[NT];

    const int pair  = blockIdx.x >> 2;
    const int chunk = blockIdx.x & 3;
    const int b     = pair / A_;
    const int tid   = threadIdx.x;
    const int lane  = tid & 31;
    const int warp  = tid >> 5;

    const int start = anchor_end[pair] + 1;

    s_m[tid] = 0.0f;
    __syncthreads();

    const float* abase = anchor_repr + (size_t)pair * D_ + chunk * DC;
    const float4 a0 = reinterpret_cast<const float4*>(abase)[lane];
    const float4 a1 = reinterpret_cast<const float4*>(abase)[lane + 32];

    const float* hbase = hidden + ((size_t)(b * T_ + start)) * D_ + chunk * DC;

    float4 m0 = make_float4(0,0,0,0), m1 = make_float4(0,0,0,0);

    for (int h = warp; h < H_; h += 8) {
        const float4* row = reinterpret_cast<const float4*>(hbase + (size_t)h * D_);
        float4 f0 = row[lane];
        float4 f1 = row[lane + 32];
        m0.x += f0.x; m0.y += f0.y; m0.z += f0.z; m0.w += f0.w;
        m1.x += f1.x; m1.y += f1.y; m1.z += f1.z; m1.w += f1.w;
        float dx, dy, dz, dw;
        dx = f0.x - a0.x; dy = f0.y - a0.y; dz = f0.z - a0.z; dw = f0.w - a0.w;
        float ss = dx*dx + dy*dy + dz*dz + dw*dw;
        dx = f1.x - a1.x; dy = f1.y - a1.y; dz = f1.z - a1.z; dw = f1.w - a1.w;
        ss += dx*dx + dy*dy + dz*dz + dw*dw;
        #pragma unroll
        for (int o = 16; o > 0; o >>= 1)
            ss += __shfl_xor_sync(0xffffffffu, ss, o);
        if (lane == 0) g_ss[chunk][pair][h] = ss;
    }

    // combine per-warp row-sums into chunk sum (8-way smem atomics, trivial)
    atomicAdd(&s_m[lane*4 + 0],        m0.x);
    atomicAdd(&s_m[lane*4 + 1],        m0.y);
    atomicAdd(&s_m[lane*4 + 2],        m0.z);
    atomicAdd(&s_m[lane*4 + 3],        m0.w);
    atomicAdd(&s_m[(lane+32)*4 + 0],   m1.x);
    atomicAdd(&s_m[(lane+32)*4 + 1],   m1.y);
    atomicAdd(&s_m[(lane+32)*4 + 2],   m1.z);
    atomicAdd(&s_m[(lane+32)*4 + 3],   m1.w);
    __syncthreads();

    const float m  = s_m[tid];     // raw row-sum (not /H) for d = chunk*DC + tid
    const float av = abase[tid];   // L1-hot: anchor chunk was just read
    float dotv = blockReduceSum(m * av,  s_red, tid);
    float nf2v = blockReduceSum(m * m,   s_red, tid);
    float na2v = blockReduceSum(av * av, s_red, tid);
    if (tid == 0) {
        g_dot[chunk][pair] = dotv;
        g_nf2[chunk][pair] = nf2v;
        g_na2[chunk][pair] = na2v;
    }
}

// ---------------------------------------------------------------------------
// Kernel 2: combine partials + all token/window logic. grid = NPAIR.
// ---------------------------------------------------------------------------
__global__ __launch_bounds__(NT, 2)
void cm_light(const int* __restrict__ input_ids,
              const int* __restrict__ anchor_end,
              float*     __restrict__ out)
{
    __shared__ float s_red[NT];
    __shared__ int   s_ftok[H_];
    __shared__ int   s_span[S_];
    __shared__ int   s_alias[64];
    __shared__ int   s_root, s_has, s_ffmask;
    __shared__ float s_invdenom;
    __shared__ float s_sim;

    const int pair = blockIdx.x;
    const int b = pair / A_;
    const int tid = threadIdx.x;

    const int aend  = anchor_end[pair];
    const int start = aend + 1;

    if (tid < 64) s_alias[tid] = (int)c_alias[tid];
    if (tid < H_) s_ftok[tid] = input_ids[b * T_ + start + tid];
    if (tid < S_) s_span[tid] = input_ids[b * T_ + aend - S_ + 1 + tid];
    __syncthreads();

    // future_shift: thread tid = row h
    float ssrow = g_ss[0][pair][tid] + g_ss[1][pair][tid]
                + g_ss[2][pair][tid] + g_ss[3][pair][tid];
    const float invH = 1.0f / (float)H_;
    float shift_sum = blockReduceSum(sqrtf(ssrow), s_red, tid);
    const float future_shift = shift_sum * invH;

    // cosine similarity from chunk partials
    if (tid == 0) {
        float dot = g_dot[0][pair] + g_dot[1][pair] + g_dot[2][pair] + g_dot[3][pair];
        float nf2 = g_nf2[0][pair] + g_nf2[1][pair] + g_nf2[2][pair] + g_nf2[3][pair];
        float na2 = g_na2[0][pair] + g_na2[1][pair] + g_na2[2][pair] + g_na2[3][pair];
        const float eps = 1e-8f;
        float nr = fmaxf(sqrtf(na2), eps);
        float nf = fmaxf(sqrtf(nf2 * invH * invH), eps);
        s_sim = (dot * invH) / (nr * nf);
    }

    // token_c (all 256 threads, H_ == NT)
    const int anchor_tok = s_span[S_ - 1];
    float teq = (s_ftok[tid] == anchor_tok) ? 1.0f : 0.0f;
    teq = blockReduceSum(teq, s_red, tid);
    const float token_c = 1.0f - teq * invH;

    const float sim = s_sim;
    const float hidden_c = fmaxf(0.0f, (1.0f - sim) * 0.5f);

    // span analysis (single thread; trivial)
    if (tid == 0) {
        int ffmask = 0, denom = 0;
        #pragma unroll
        for (int s = 0; s < S_; s++) {
            bool first = true;
            for (int j = 0; j < s; j++)
                if (s_span[j] == s_span[s]) { first = false; break; }
            if (first) { ffmask |= (1 << s); denom++; }
        }
        int first_root = -1;
        #pragma unroll
        for (int s = 0; s < S_; s++) {
            int al = s_alias[s_span[s]];
            if (al >= 0) { first_root = al; break; }
        }
        int root;
        if (first_root >= 0) {
            root = first_root;
        } else {
            int maxc = 0;
            int counts[S_];
            #pragma unroll
            for (int s = 0; s < S_; s++) {
                int c = 0;
                for (int j = 0; j < S_; j++) c += (s_span[j] == s_span[s]);
                counts[s] = c;
                maxc = max(maxc, c);
            }
            int mode = 64;
            #pragma unroll
            for (int s = 0; s < S_; s++)
                if (counts[s] == maxc) mode = min(mode, s_span[s]);
            root = mode;
        }
        s_root = root;
        s_has = (compat_mask_of(root) != 0ull) ? 1 : 0;
        s_ffmask = ffmask;
        s_invdenom = 1.0f / (float)denom;
    }
    __syncthreads();

    const int root = s_root;
    const int has = s_has;
    const int ffmask = s_ffmask;
    const float invdenom = s_invdenom;
    const unsigned long long cmask = compat_mask_of(root);

    float sims = 0.0f, rp_mean = 0.0f, regime = 0.0f, hit06 = 0.0f, best_v = -1e30f;
    if (tid < W_) {
        float ex = 0.0f, pos = 0.0f, rp = 0.0f, ac = 0.0f, hd = 0.0f;
        unsigned long long wmask = 0ull;
        #pragma unroll
        for (int s = 0; s < S_; s++) {
            int tok = s_ftok[tid + s];
            wmask |= (1ull << tok);
            float eq = (tok == s_span[s]) ? 1.0f : 0.0f;
            ex  += eq;
            pos += eq * ((1.0f - 0.04f * (float)s) * (1.0f / 11.2f));
            rp  += (tok == root) ? 1.0f : 0.0f;
            ac  += (s_alias[tok] == root) ? 1.0f : 0.0f;
            hd  += (float)((cmask >> tok) & 1ull);
        }
        float ov = 0.0f;
        #pragma unroll
        for (int s = 0; s < S_; s++) {
            if (((ffmask >> s) & 1) && ((wmask >> s_span[s]) & 1ull)) ov += 1.0f;
        }
        ov *= invdenom;
        const float inv16 = 1.0f / 16.0f;
        ex *= inv16; ac *= inv16; hd *= inv16;
        rp_mean = rp * inv16;

        regime = has ? (0.55f*hd + 0.2f*ov + 0.15f*ac + 0.1f*rp_mean)
                     : (0.45f*ex + 0.3f*ov + 0.1f*ac + 0.15f*rp_mean);
        sims = 0.25f*ex + 0.15f*ov + 0.35f*pos + 0.25f*regime;
        best_v = sims;
        hit06 = (sims >= 0.6f) ? 1.0f : 0.0f;
    }

    float best     = blockReduceMax(best_v,  s_red, tid);
    float sum_sims = blockReduceSum(sims,    s_red, tid);
    float sum_rp   = blockReduceSum(rp_mean, s_red, tid);
    float sum_reg  = blockReduceSum(regime,  s_red, tid);
    float cnt06    = blockReduceSum(hit06,   s_red, tid);

    if (tid == 0) {
        const float invW = 1.0f / (float)W_;
        float mrp = sum_rp  * invW;
        float mrc = sum_reg * invW;
        float mean_sims = sum_sims * invW;
        float dmass = cnt06 * invW;
        float dcoh = 0.6f*mean_sims + 0.25f*mrp + 0.15f*mrc;
        float pattern_c = 1.0f - (0.6f*best + 0.2f*mrp + 0.2f*mrc);
        float contr = 0.2f*hidden_c + 0.2f*token_c + 0.6f*pattern_c;
        contr = fminf(fmaxf(contr, 0.0f), 1.0f);

        out[0 * NPAIR + pair] = contr;
        out[1 * NPAIR + pair] = future_shift;
        out[2 * NPAIR + pair] = sim;
        out[3 * NPAIR + pair] = hidden_c;
        out[4 * NPAIR + pair] = token_c;
        out[5 * NPAIR + pair] = pattern_c;
        out[6 * NPAIR + pair] = dmass;
        out[7 * NPAIR + pair] = dcoh;
    }
}

extern "C" void kernel_launch(void* const* d_in, const int* in_sizes, int n_in,
                              void* d_out, int out_size) {
    const float* hidden      = (const float*)d_in[0];
    const float* anchor_repr = (const float*)d_in[1];
    const int*   input_ids   = (const int*)d_in[2];
    const int*   anchor_end  = (const int*)d_in[3];
    float*       out         = (float*)d_out;
    cm_heavy<<<NPAIR * NCHUNK, NT>>>(hidden, anchor_repr, anchor_end);
    cm_light<<<NPAIR, NT>>>(input_ids, anchor_end, out);
}